// round 2
// baseline (speedup 1.0000x reference)
#include <cuda_runtime.h>

// orig_fea [256, 300, 256] f32; ind0/ind1 [32,32,4] i32; W1a/W1b [256,256];
// b1[256]; W2[256,1]; b2[1]. L=128, pool=1200.
#define LN   128
#define DD   256
#define HH   256
#define NUMG 32
#define BAG  300

typedef unsigned long long u64;

// Scratch: h0/h1 transposed: [side][n][h][a]  (8 MB)
__device__ float g_hT[2][NUMG][HH][LN];

__device__ __forceinline__ u64 pack2(float lo, float hi) {
    u64 r; asm("mov.b64 %0, {%1,%2};" : "=l"(r) : "f"(lo), "f"(hi)); return r;
}
__device__ __forceinline__ float2 unpack2(u64 v) {
    float2 r; asm("mov.b64 {%0,%1}, %2;" : "=f"(r.x), "=f"(r.y) : "l"(v)); return r;
}
__device__ __forceinline__ u64 add2(u64 a, u64 b) {
    u64 r; asm("add.rn.f32x2 %0, %1, %2;" : "=l"(r) : "l"(a), "l"(b)); return r;
}
__device__ __forceinline__ u64 fma2(u64 a, u64 b, u64 c) {
    u64 r; asm("fma.rn.f32x2 %0, %1, %2, %3;" : "=l"(r) : "l"(a), "l"(b), "l"(c)); return r;
}

// ---------------------------------------------------------------------------
// Kernel 1: gather + GEMM with W1a/W1b, f32x2 packed, double-buffered.
// grid (2,1,64): x = h-tile(128), z = side*32+n. 128 blocks = 1 wave.
// block 256: ty=t/16 -> 8 a's (packed as 4 f32x2 pairs), tx=t%16 -> 8 h's.
// ---------------------------------------------------------------------------
__global__ __launch_bounds__(256)
void gemm_gather_kernel(const float* __restrict__ orig,
                        const int*   __restrict__ ind0,
                        const int*   __restrict__ ind1,
                        const float* __restrict__ W1a,
                        const float* __restrict__ W1b,
                        const float* __restrict__ b1)
{
    const int side = blockIdx.z >> 5;
    const int n    = blockIdx.z & 31;
    const int h0   = blockIdx.x * 128;
    const int*   __restrict__ ind = side ? ind1 : ind0;
    const float* __restrict__ W   = side ? W1b  : W1a;

    __shared__ __align__(16) float As[2][8][132];  // [buf][k][a]
    __shared__ u64                 Bs[2][8][132];  // [buf][k][h] pre-dup {b,b}
    __shared__ int rowoff[128];

    const int t = threadIdx.x;
    if (t < 128) {
        int p = ind[n * LN + t] + BAG * (t & 3);       // pool index
        rowoff[t] = ((n * 2 + side) * 1200 + p) * DD;  // float offset
    }
    __syncthreads();

    const int la  = t & 127, lkq = t >> 7;   // A load: a, k-quad(0/1)
    const int bk  = t >> 5,  bq  = t & 31;   // B load: k, h-quad
    const int ty  = t >> 4,  tx  = t & 15;   // compute

    u64 acc[4][8];
#pragma unroll
    for (int j = 0; j < 4; j++)
#pragma unroll
        for (int i = 0; i < 8; i++) acc[j][i] = 0ULL;

    // prologue: chunk 0
    {
        float4 av = *(const float4*)(orig + rowoff[la] + lkq * 4);
        float4 bv = *(const float4*)(W + bk * HH + h0 + bq * 4);
        As[0][lkq * 4 + 0][la] = av.x;
        As[0][lkq * 4 + 1][la] = av.y;
        As[0][lkq * 4 + 2][la] = av.z;
        As[0][lkq * 4 + 3][la] = av.w;
        Bs[0][bk][bq * 4 + 0] = pack2(bv.x, bv.x);
        Bs[0][bk][bq * 4 + 1] = pack2(bv.y, bv.y);
        Bs[0][bk][bq * 4 + 2] = pack2(bv.z, bv.z);
        Bs[0][bk][bq * 4 + 3] = pack2(bv.w, bv.w);
    }
    __syncthreads();

    int buf = 0;
    for (int c = 0; c < 32; c++) {
        float4 av2, bv2;
        if (c < 31) {
            int k0 = (c + 1) * 8;
            av2 = *(const float4*)(orig + rowoff[la] + k0 + lkq * 4);
            bv2 = *(const float4*)(W + (k0 + bk) * HH + h0 + bq * 4);
        }
#pragma unroll
        for (int kk = 0; kk < 8; kk++) {
            u64 a2[4];
#pragma unroll
            for (int p = 0; p < 4; p++)
                a2[p] = *(const u64*)&As[buf][kk][ty * 8 + p * 2];
#pragma unroll
            for (int i = 0; i < 8; i++) {
                u64 b2 = Bs[buf][kk][tx * 8 + i];
#pragma unroll
                for (int j = 0; j < 4; j++)
                    acc[j][i] = fma2(a2[j], b2, acc[j][i]);
            }
        }
        if (c < 31) {
            int nb = buf ^ 1;
            As[nb][lkq * 4 + 0][la] = av2.x;
            As[nb][lkq * 4 + 1][la] = av2.y;
            As[nb][lkq * 4 + 2][la] = av2.z;
            As[nb][lkq * 4 + 3][la] = av2.w;
            Bs[nb][bk][bq * 4 + 0] = pack2(bv2.x, bv2.x);
            Bs[nb][bk][bq * 4 + 1] = pack2(bv2.y, bv2.y);
            Bs[nb][bk][bq * 4 + 2] = pack2(bv2.z, bv2.z);
            Bs[nb][bk][bq * 4 + 3] = pack2(bv2.w, bv2.w);
            buf = nb;
            __syncthreads();
        }
    }

    // epilogue: +b1 (side 0 only), write transposed [h][a]
    u64 bias2[8];
#pragma unroll
    for (int i = 0; i < 8; i++) {
        float b = (side == 0) ? b1[h0 + tx * 8 + i] : 0.f;
        bias2[i] = pack2(b, b);
    }
#pragma unroll
    for (int i = 0; i < 8; i++) {
        int h = h0 + tx * 8 + i;
#pragma unroll
        for (int j = 0; j < 4; j++) {
            u64 v = add2(acc[j][i], bias2[i]);
            *(u64*)&g_hT[side][n][h][ty * 8 + j * 2] = v;
        }
    }
}

// ---------------------------------------------------------------------------
// Kernel 2: scores[n,m,l] = sum_{4x4 patch, h} relu(x+y)*W2 + 16*b2.
// Packed trick: relu(s)*w == (s + |s|) * (0.5*w), bit-exact.
// grid 128 = 32 n * 4 a-tiles; block 256: ty(8)->4 a, tx(32)->4 b (2 pairs).
// ---------------------------------------------------------------------------
__global__ __launch_bounds__(256)
void pairwise_kernel(const float* __restrict__ W2,
                     const float* __restrict__ b2,
                     float* __restrict__ out,
                     int write_pairs)
{
    const int n  = blockIdx.x >> 2;
    const int at = blockIdx.x & 3;
    const int a0 = at * 32;
    const int t  = threadIdx.x;
    const int ty = t >> 5;   // 0..7
    const int tx = t & 31;   // 0..31

    __shared__ u64 xs2[32][33];                    // [h][a] pre-dup {x,x}
    __shared__ __align__(16) float ys[32][132];    // [h][b]
    __shared__ u64 ws2[32];                        // {0.5w, 0.5w}

    u64 acc[4][2];
#pragma unroll
    for (int j = 0; j < 4; j++) { acc[j][0] = 0ULL; acc[j][1] = 0ULL; }

    for (int hc = 0; hc < HH; hc += 32) {
        {
            int hh = t >> 3, q = (t & 7) * 4;
            float4 v = *(const float4*)&g_hT[0][n][hc + hh][a0 + q];
            xs2[hh][q + 0] = pack2(v.x, v.x);
            xs2[hh][q + 1] = pack2(v.y, v.y);
            xs2[hh][q + 2] = pack2(v.z, v.z);
            xs2[hh][q + 3] = pack2(v.w, v.w);
        }
#pragma unroll
        for (int r = 0; r < 4; r++) {
            int id = t + 256 * r;
            int hh = id >> 5, q = (id & 31) * 4;
            *(float4*)&ys[hh][q] = *(const float4*)&g_hT[1][n][hc + hh][q];
        }
        if (t < 32) {
            float w = 0.5f * W2[hc + t];
            ws2[t] = pack2(w, w);
        }
        __syncthreads();

#pragma unroll 4
        for (int hh = 0; hh < 32; hh++) {
            u64 wh = ws2[hh];
            u64 x2[4];
#pragma unroll
            for (int j = 0; j < 4; j++) x2[j] = xs2[hh][ty * 4 + j];
            u64 y2[2];
            y2[0] = *(const u64*)&ys[hh][tx * 4 + 0];
            y2[1] = *(const u64*)&ys[hh][tx * 4 + 2];
#pragma unroll
            for (int j = 0; j < 4; j++)
#pragma unroll
                for (int i2 = 0; i2 < 2; i2++) {
                    u64 s = add2(x2[j], y2[i2]);
                    u64 u = add2(s, s & 0x7FFFFFFF7FFFFFFFULL);  // 2*relu(s)
                    acc[j][i2] = fma2(u, wh, acc[j][i2]);
                }
        }
        __syncthreads();
    }

    float s = 0.f;
#pragma unroll
    for (int j = 0; j < 4; j++)
#pragma unroll
        for (int i2 = 0; i2 < 2; i2++) {
            float2 v = unpack2(acc[j][i2]);
            s += v.x + v.y;
        }
    s += 16.f * b2[0];

    const int m = at * 8 + ty;
    const int l = tx;
    out[n * 1024 + m * 32 + l] = s;

    if (write_pairs) {
        int id  = blockIdx.x * 256 + t;      // 0..32767, writes 2 floats
        int idx = id & 1023;
        float2 pv = make_float2((float)(idx >> 5), (float)(idx & 31));
        *(float2*)&out[NUMG * 1024 + 2 * id] = pv;
    }
}

extern "C" void kernel_launch(void* const* d_in, const int* in_sizes, int n_in,
                              void* d_out, int out_size)
{
    const float* orig = (const float*)d_in[0];
    const int*   ind0 = (const int*)d_in[1];
    const int*   ind1 = (const int*)d_in[2];
    int i = 3;
    if (n_in >= 9 && in_sizes[3] == 1) i = 4;   // scalar k materialized
    const float* W1a = (const float*)d_in[i + 0];
    const float* W1b = (const float*)d_in[i + 1];
    const float* b1  = (const float*)d_in[i + 2];
    const float* W2  = (const float*)d_in[i + 3];
    const float* b2  = (const float*)d_in[i + 4];
    float* out = (float*)d_out;

    const int scores_elems = NUMG * 1024;
    const int pairs_elems  = NUMG * 1024 * 2;
    int write_pairs = (out_size >= scores_elems + pairs_elems) ? 1 : 0;

    dim3 g1(2, 1, 64);
    gemm_gather_kernel<<<g1, 256>>>(orig, ind0, ind1, W1a, W1b, b1);
    pairwise_kernel<<<NUMG * 4, 256>>>(W2, b2, out, write_pairs);
}

// round 5
// speedup vs baseline: 1.8926x; 1.8926x over previous
#include <cuda_runtime.h>

// orig_fea [256, 300, 256] f32; ind0/ind1 [32,32,4] i32; W1a/W1b [256,256];
// b1[256]; W2[256,1]; b2[1]. L=128, pool=1200.
#define LN   128
#define DD   256
#define HH   256
#define NUMG 32
#define BAG  300

// Scratch: h0/h1 transposed: [side][n][h][a]  (8 MB)
__device__ float g_hT[2][NUMG][HH][LN];

// ---------------------------------------------------------------------------
// Kernel 1: gather + GEMM, scalar FFMA, register-staged double buffering.
// grid (4,2,64): x = h-tile(64), y = a-tile(64), z = side*32+n. 512 blocks.
// block 256: ty=t/16 -> 4 a's, tx=t%16 -> 4 h's. 16 FFMA per kk per thread.
// ---------------------------------------------------------------------------
__global__ __launch_bounds__(256)
void gemm_gather_kernel(const float* __restrict__ orig,
                        const int*   __restrict__ ind0,
                        const int*   __restrict__ ind1,
                        const float* __restrict__ W1a,
                        const float* __restrict__ W1b,
                        const float* __restrict__ b1)
{
    const int side = blockIdx.z >> 5;
    const int n    = blockIdx.z & 31;
    const int m0   = blockIdx.y * 64;   // a-tile
    const int h0   = blockIdx.x * 64;   // h-tile
    const int*   __restrict__ ind = side ? ind1 : ind0;
    const float* __restrict__ W   = side ? W1b  : W1a;

    __shared__ float As[2][16][68];   // [buf][k][a]
    __shared__ float Bs[2][16][68];   // [buf][k][h]
    __shared__ int   rowoff[64];

    const int t = threadIdx.x;
    if (t < 64) {
        int a = m0 + t;
        int p = ind[n * LN + a] + BAG * (a & 3);       // pool index [0,1200)
        rowoff[t] = ((n * 2 + side) * 1200 + p) * DD;  // float offset
    }
    __syncthreads();

    const int lm = t >> 2, lq = t & 3;    // A load: a, k-quad
    const int bk = t >> 4, bq = t & 15;   // B load: k, h-quad
    const int ty = t >> 4, tx = t & 15;   // compute

    float acc[4][4];
#pragma unroll
    for (int j = 0; j < 4; j++)
#pragma unroll
        for (int i = 0; i < 4; i++) acc[j][i] = 0.f;

    // prologue: chunk 0
    {
        float4 av = *(const float4*)(orig + rowoff[lm] + lq * 4);
        float4 bv = *(const float4*)(W + bk * HH + h0 + bq * 4);
        As[0][lq * 4 + 0][lm] = av.x;
        As[0][lq * 4 + 1][lm] = av.y;
        As[0][lq * 4 + 2][lm] = av.z;
        As[0][lq * 4 + 3][lm] = av.w;
        *(float4*)&Bs[0][bk][bq * 4] = bv;
    }
    __syncthreads();

    int buf = 0;
#pragma unroll 1
    for (int c = 0; c < 16; c++) {
        float4 av2, bv2;
        if (c < 15) {
            int k0 = (c + 1) * 16;
            av2 = *(const float4*)(orig + rowoff[lm] + k0 + lq * 4);
            bv2 = *(const float4*)(W + (k0 + bk) * HH + h0 + bq * 4);
        }
#pragma unroll
        for (int kk = 0; kk < 16; kk++) {
            float4 a4 = *(const float4*)&As[buf][kk][ty * 4];
            float4 b4 = *(const float4*)&Bs[buf][kk][tx * 4];
            float aa[4] = {a4.x, a4.y, a4.z, a4.w};
            float bb[4] = {b4.x, b4.y, b4.z, b4.w};
#pragma unroll
            for (int j = 0; j < 4; j++)
#pragma unroll
                for (int i = 0; i < 4; i++)
                    acc[j][i] = fmaf(aa[j], bb[i], acc[j][i]);
        }
        if (c < 15) {
            int nb = buf ^ 1;
            As[nb][lq * 4 + 0][lm] = av2.x;
            As[nb][lq * 4 + 1][lm] = av2.y;
            As[nb][lq * 4 + 2][lm] = av2.z;
            As[nb][lq * 4 + 3][lm] = av2.w;
            *(float4*)&Bs[nb][bk][bq * 4] = bv2;
            __syncthreads();
            buf = nb;
        }
    }

    // epilogue: +b1 (side 0 only), write transposed [h][a]
    float bias[4] = {0.f, 0.f, 0.f, 0.f};
    if (side == 0) {
        float4 bv = *(const float4*)&b1[h0 + tx * 4];
        bias[0] = bv.x; bias[1] = bv.y; bias[2] = bv.z; bias[3] = bv.w;
    }
#pragma unroll
    for (int i = 0; i < 4; i++) {
        float4 v;
        v.x = acc[0][i] + bias[i];
        v.y = acc[1][i] + bias[i];
        v.z = acc[2][i] + bias[i];
        v.w = acc[3][i] + bias[i];
        *(float4*)&g_hT[side][n][h0 + tx * 4 + i][m0 + ty * 4] = v;
    }
}

// ---------------------------------------------------------------------------
// Kernel 2: scores[n,m,l] = sum_{4x4 patch, h} relu(x+y)*W2 + 16*b2.
// grid 256 = 32 n * 8 a-tiles (16 a each); block 256:
//   tx = t&31 (b patch col), ty = (t>>5)&3 (a patch row), th = t>>7 (h split).
// Each (tx,ty) patch handled by 2 threads interleaving hh; combine via smem.
// xs resident for all 256 h; ys double-buffered (1 sync/chunk).
// Static smem: xs 16KB + ys 32KB = 48KB; reduction aliases dead ys buffer.
// ---------------------------------------------------------------------------
__global__ __launch_bounds__(256)
void pairwise_kernel(const float* __restrict__ W2,
                     const float* __restrict__ b2,
                     float* __restrict__ out,
                     int write_pairs)
{
    const int bid = blockIdx.x;
    const int n   = bid >> 3;
    const int at  = bid & 7;
    const int a0  = at * 16;
    const int t   = threadIdx.x;
    const int tx  = t & 31;
    const int ty  = (t >> 5) & 3;
    const int th  = t >> 7;

    __shared__ float4 xs4[256][4];      // [h][a-quad]  16KB
    __shared__ float4 ys4[2][32][32];   // [buf][h][b-quad]  32KB

    // load xs: all 256 h rows, 16 a's
#pragma unroll
    for (int r = 0; r < 4; r++) {
        int id = t + 256 * r;
        int hh = id >> 2, q = id & 3;
        xs4[hh][q] = *(const float4*)&g_hT[0][n][hh][a0 + q * 4];
    }
    // prologue: ys chunk 0
    {
        int c4 = t & 31, hh = t >> 5;
#pragma unroll
        for (int r = 0; r < 4; r++)
            ys4[0][hh + r * 8][c4] = *(const float4*)&g_hT[1][n][hh + r * 8][c4 * 4];
    }
    __syncthreads();

    float acc[4][4];
#pragma unroll
    for (int j = 0; j < 4; j++)
#pragma unroll
        for (int i = 0; i < 4; i++) acc[j][i] = 0.f;

    int buf = 0;
#pragma unroll 1
    for (int hc = 0; hc < 8; hc++) {
        float4 st[4];
        if (hc < 7) {
            int c4 = t & 31, hh = t >> 5;
#pragma unroll
            for (int r = 0; r < 4; r++)
                st[r] = *(const float4*)&g_hT[1][n][(hc + 1) * 32 + hh + r * 8][c4 * 4];
        }
#pragma unroll
        for (int u = 0; u < 16; u++) {
            int hh = th + u * 2;
            int hs = hc * 32 + hh;
            float  w  = __ldg(&W2[hs]);
            float4 x4 = xs4[hs][ty];
            float4 y4 = ys4[buf][hh][tx];
            float xa[4] = {x4.x, x4.y, x4.z, x4.w};
            float yb[4] = {y4.x, y4.y, y4.z, y4.w};
#pragma unroll
            for (int j = 0; j < 4; j++)
#pragma unroll
                for (int i = 0; i < 4; i++)
                    acc[j][i] = fmaf(fmaxf(xa[j] + yb[i], 0.f), w, acc[j][i]);
        }
        if (hc < 7) {
            int c4 = t & 31, hh = t >> 5, nb = buf ^ 1;
#pragma unroll
            for (int r = 0; r < 4; r++)
                ys4[nb][hh + r * 8][c4] = st[r];
            __syncthreads();
            buf = nb;
        }
    }
    // after loop buf==1, so ys4[0] is dead -> reuse as reduction scratch
    float* red = (float*)&ys4[0][0][0];   // 128 threads x 16 floats
    __syncthreads();
    if (th == 1) {
        int r0 = (t & 127) * 17;   // pad-17 to dodge conflicts
#pragma unroll
        for (int j = 0; j < 4; j++)
#pragma unroll
            for (int i = 0; i < 4; i++) red[r0 + j * 4 + i] = acc[j][i];
    }
    __syncthreads();
    if (th == 0) {
        int r0 = t * 17;
        float s = 0.f;
#pragma unroll
        for (int j = 0; j < 4; j++)
#pragma unroll
            for (int i = 0; i < 4; i++) s += acc[j][i] + red[r0 + j * 4 + i];
        s += 16.f * __ldg(b2);
        const int m = at * 4 + ty;
        out[n * 1024 + m * 32 + tx] = s;
    }

    if (write_pairs) {
        int id    = bid * 256 + t;     // 0..65535, one float each
        int pi    = id >> 1;
        int which = id & 1;
        int idx   = pi & 1023;
        int v = which ? (idx & 31) : (idx >> 5);
        out[NUMG * 1024 + id] = (float)v;
    }
}

extern "C" void kernel_launch(void* const* d_in, const int* in_sizes, int n_in,
                              void* d_out, int out_size)
{
    const float* orig = (const float*)d_in[0];
    const int*   ind0 = (const int*)d_in[1];
    const int*   ind1 = (const int*)d_in[2];
    int i = 3;
    if (n_in >= 9 && in_sizes[3] == 1) i = 4;   // scalar k materialized
    const float* W1a = (const float*)d_in[i + 0];
    const float* W1b = (const float*)d_in[i + 1];
    const float* b1  = (const float*)d_in[i + 2];
    const float* W2  = (const float*)d_in[i + 3];
    const float* b2  = (const float*)d_in[i + 4];
    float* out = (float*)d_out;

    const int scores_elems = NUMG * 1024;
    const int pairs_elems  = NUMG * 1024 * 2;
    int write_pairs = (out_size >= scores_elems + pairs_elems) ? 1 : 0;

    dim3 g1(4, 2, 64);
    gemm_gather_kernel<<<g1, 256>>>(orig, ind0, ind1, W1a, W1b, b1);
    pairwise_kernel<<<NUMG * 8, 256>>>(W2, b2, out, write_pairs);
}

// round 7
// speedup vs baseline: 2.2843x; 1.2070x over previous
#include <cuda_runtime.h>
#include <cuda_bf16.h>
#include <cstdint>

// orig_fea [256, 300, 256] f32; ind0/ind1 [32,32,4] i32; W1a/W1b [256,256];
// b1[256]; W2[256,1]; b2[1]. L=128, pool=1200.
#define LN   128
#define DD   256
#define HH   256
#define NUMG 32
#define BAG  300

// Scratch: h0/h1 transposed: [side][n][h][a]  (8 MB)
__device__ float g_hT[2][NUMG][HH][LN];
// W split into bf16 hi/lo, transposed to [side][part][h][k] as u32 k-pairs (512KB)
__device__ uint32_t g_Wsp[2][2][HH][DD / 2];

// ============================ helpers ============================
__device__ __forceinline__ uint32_t smem_u32(const void* p) {
    uint32_t a;
    asm("{ .reg .u64 t; cvta.to.shared.u64 t, %1; cvt.u32.u64 %0, t; }"
        : "=r"(a) : "l"(p));
    return a;
}
// f32 pair -> bf16x2 (low half = x0); also return rounded values as f32
__device__ __forceinline__ uint32_t cvt_pair(float x0, float x1, float& h0f, float& h1f) {
    uint32_t r;
    asm("cvt.rn.bf16x2.f32 %0, %1, %2;" : "=r"(r) : "f"(x1), "f"(x0));
    h0f = __uint_as_float(r << 16);
    h1f = __uint_as_float(r & 0xFFFF0000u);
    return r;
}
__device__ __forceinline__ uint32_t cvt_pair_n(float x0, float x1) {
    uint32_t r;
    asm("cvt.rn.bf16x2.f32 %0, %1, %2;" : "=r"(r) : "f"(x1), "f"(x0));
    return r;
}
__device__ __forceinline__ void ldsm4(uint32_t* r, uint32_t addr) {
    asm volatile("ldmatrix.sync.aligned.m8n8.x4.shared.b16 {%0,%1,%2,%3}, [%4];"
        : "=r"(r[0]), "=r"(r[1]), "=r"(r[2]), "=r"(r[3]) : "r"(addr));
}
__device__ __forceinline__ void mma16816(float* d, const uint32_t* a,
                                         uint32_t b0, uint32_t b1) {
    asm volatile("mma.sync.aligned.m16n8k16.row.col.f32.bf16.bf16.f32 "
        "{%0,%1,%2,%3}, {%4,%5,%6,%7}, {%8,%9}, {%0,%1,%2,%3};"
        : "+f"(d[0]), "+f"(d[1]), "+f"(d[2]), "+f"(d[3])
        : "r"(a[0]), "r"(a[1]), "r"(a[2]), "r"(a[3]), "r"(b0), "r"(b1));
}
// XOR swizzle: rows of 128B, 16B atoms permuted by row%8 -> conflict-free LDSM
#define SWZ(row, kb) ((row) * 128 + ((kb) ^ (((row) & 7) << 4)))

// ---------------------------------------------------------------------------
// Prep: W1a/W1b [k][h] -> g_Wsp[side][hi/lo][h][k-pairs] bf16 (smem transpose).
// grid 32 = side*16 + (kt*4 + ht), block 256. 64x64 tiles.
// ---------------------------------------------------------------------------
__global__ __launch_bounds__(256)
void prep_w_kernel(const float* __restrict__ W1a, const float* __restrict__ W1b)
{
    __shared__ unsigned short shi[64][65], slo[64][65];
    const int b    = blockIdx.x;
    const int side = b >> 4;
    const int tile = b & 15;
    const int k0   = (tile >> 2) * 64;
    const int h0v  = (tile & 3) * 64;
    const float* __restrict__ W = side ? W1b : W1a;
    const int t   = threadIdx.x;
    const int kl  = t >> 2;
    const int hl0 = (t & 3) * 16;
#pragma unroll
    for (int q = 0; q < 4; q++) {
        float4 v = *(const float4*)&W[(k0 + kl) * HH + h0v + hl0 + q * 4];
        float xs[4] = {v.x, v.y, v.z, v.w};
#pragma unroll
        for (int r = 0; r < 4; r++) {
            __nv_bfloat16 h = __float2bfloat16(xs[r]);
            float hf = __bfloat162float(h);
            __nv_bfloat16 l = __float2bfloat16(xs[r] - hf);
            shi[kl][hl0 + q * 4 + r] = __bfloat16_as_ushort(h);
            slo[kl][hl0 + q * 4 + r] = __bfloat16_as_ushort(l);
        }
    }
    __syncthreads();
    const int hl = t >> 2;
    const int kc = (t & 3) * 16;
#pragma unroll
    for (int j = 0; j < 8; j++) {
        int k = kc + 2 * j;
        uint32_t uhi = (uint32_t)shi[k][hl] | ((uint32_t)shi[k + 1][hl] << 16);
        uint32_t ulo = (uint32_t)slo[k][hl] | ((uint32_t)slo[k + 1][hl] << 16);
        g_Wsp[side][0][h0v + hl][(k0 + k) >> 1] = uhi;
        g_Wsp[side][1][h0v + hl][(k0 + k) >> 1] = ulo;
    }
}

// ---------------------------------------------------------------------------
// Kernel 1: mma.sync bf16 split-precision GEMM.
// grid 256 = side(2) x n(32) x h-quad(4, 64 h each). block 256 = 8 warps
// (warp_m 0..3 -> 32 a, warp_n 0..1 -> 32 h). K staged in chunks of 64 into
// swizzled smem: Ahi/Alo [128][64]bf16 (16KB ea), Bhi/Blo [64][64] (8KB ea).
// Per k16 step: 4 A-ldsm.x4 + 4 B-ldsm.x4, 24 mma (3 terms x 2m x 4n).
// ---------------------------------------------------------------------------
__global__ __launch_bounds__(256)
void gemm_mma_kernel(const float* __restrict__ orig,
                     const int*   __restrict__ ind0,
                     const int*   __restrict__ ind1,
                     const float* __restrict__ bias1)
{
    extern __shared__ char dsm[];
    __shared__ int rowoff[128];

    const int t = threadIdx.x, l = t & 31, w = t >> 5;
    const int b    = blockIdx.x;
    const int side = b >> 7;
    const int n    = (b >> 2) & 31;
    const int h0   = (b & 3) * 64;
    const int m0   = (w & 3) * 32;
    const int n0   = (w >> 2) * 32;

    const uint32_t smb   = smem_u32(dsm);
    const int offAhi = 0, offAlo = 16384, offBhi = 32768, offBlo = 40960;

    if (t < 128) {
        const int* __restrict__ ind = side ? ind1 : ind0;
        int p = ind[n * LN + t] + BAG * (t & 3);
        rowoff[t] = ((n * 2 + side) * 1200 + p) * DD;
    }
    __syncthreads();

    const int arow  = t >> 1;
    const int halfk = t & 1;
    const int ro    = rowoff[arow];
    const int hrow  = t >> 2;

    float acc[2][4][4];
#pragma unroll
    for (int mt = 0; mt < 2; mt++)
#pragma unroll
        for (int nt = 0; nt < 4; nt++)
#pragma unroll
            for (int i = 0; i < 4; i++) acc[mt][nt][i] = 0.f;

#pragma unroll 1
    for (int c = 0; c < 4; c++) {
        // ---- stage A: 32 f32 per thread -> bf16 hi/lo, swizzled ----
        {
            const float4* ap = (const float4*)(orig + ro + c * 64 + halfk * 32);
            float4 av[8];
#pragma unroll
            for (int q = 0; q < 8; q++) av[q] = ap[q];
#pragma unroll
            for (int q2 = 0; q2 < 4; q2++) {
                float4 u = av[2 * q2], v = av[2 * q2 + 1];
                float r0, r1, r2, r3, r4, r5, r6, r7;
                uint32_t hp0 = cvt_pair(u.x, u.y, r0, r1);
                uint32_t hp1 = cvt_pair(u.z, u.w, r2, r3);
                uint32_t hp2 = cvt_pair(v.x, v.y, r4, r5);
                uint32_t hp3 = cvt_pair(v.z, v.w, r6, r7);
                uint32_t lp0 = cvt_pair_n(u.x - r0, u.y - r1);
                uint32_t lp1 = cvt_pair_n(u.z - r2, u.w - r3);
                uint32_t lp2 = cvt_pair_n(v.x - r4, v.y - r5);
                uint32_t lp3 = cvt_pair_n(v.z - r6, v.w - r7);
                int kb = halfk * 64 + q2 * 16;
                *(uint4*)(dsm + offAhi + SWZ(arow, kb)) = make_uint4(hp0, hp1, hp2, hp3);
                *(uint4*)(dsm + offAlo + SWZ(arow, kb)) = make_uint4(lp0, lp1, lp2, lp3);
            }
        }
        // ---- stage B: preconverted bf16 from g_Wsp ----
#pragma unroll
        for (int part = 0; part < 2; part++) {
            int offB = part ? offBlo : offBhi;
#pragma unroll
            for (int j = 0; j < 2; j++) {
                int qq = (t & 3) * 2 + j;
                uint4 bv = *(const uint4*)&g_Wsp[side][part][h0 + hrow][c * 32 + qq * 4];
                *(uint4*)(dsm + offB + SWZ(hrow, qq * 16)) = bv;
            }
        }
        __syncthreads();

        // ---- compute: 4 k16 steps ----
#pragma unroll
        for (int ks = 0; ks < 4; ks++) {
            const int rA  = m0 + (l & 15);
            const int rB  = n0 + (l & 15);
            const int kbL = ks * 32 + ((l >> 4) << 4);
            uint32_t ahi[2][4], alo[2][4], bhi[2][4], blo[2][4];
            ldsm4(ahi[0], smb + offAhi + SWZ(rA, kbL));
            ldsm4(ahi[1], smb + offAhi + SWZ(rA + 16, kbL));
            ldsm4(alo[0], smb + offAlo + SWZ(rA, kbL));
            ldsm4(alo[1], smb + offAlo + SWZ(rA + 16, kbL));
            ldsm4(bhi[0], smb + offBhi + SWZ(rB, kbL));
            ldsm4(bhi[1], smb + offBhi + SWZ(rB + 16, kbL));
            ldsm4(blo[0], smb + offBlo + SWZ(rB, kbL));
            ldsm4(blo[1], smb + offBlo + SWZ(rB + 16, kbL));
#pragma unroll
            for (int mt = 0; mt < 2; mt++)
#pragma unroll
                for (int pq = 0; pq < 2; pq++)
#pragma unroll
                    for (int s = 0; s < 2; s++) {
                        int nt = pq * 2 + s;
                        mma16816(acc[mt][nt], ahi[mt], bhi[pq][s], bhi[pq][s + 2]);
                        mma16816(acc[mt][nt], alo[mt], bhi[pq][s], bhi[pq][s + 2]);
                        mma16816(acc[mt][nt], ahi[mt], blo[pq][s], blo[pq][s + 2]);
                    }
        }
        __syncthreads();
    }

    // ---- epilogue: write transposed to g_hT (+b1 on side 0) ----
    const int g    = l >> 2;
    const int tid4 = l & 3;
#pragma unroll
    for (int mt = 0; mt < 2; mt++) {
        int ag = m0 + mt * 16 + g;
#pragma unroll
        for (int nt = 0; nt < 4; nt++) {
            int hg = h0 + n0 + nt * 8 + tid4 * 2;
            float bv0 = 0.f, bv1 = 0.f;
            if (side == 0) { bv0 = __ldg(&bias1[hg]); bv1 = __ldg(&bias1[hg + 1]); }
            g_hT[side][n][hg    ][ag    ] = acc[mt][nt][0] + bv0;
            g_hT[side][n][hg + 1][ag    ] = acc[mt][nt][1] + bv1;
            g_hT[side][n][hg    ][ag + 8] = acc[mt][nt][2] + bv0;
            g_hT[side][n][hg + 1][ag + 8] = acc[mt][nt][3] + bv1;
        }
    }
}

// ---------------------------------------------------------------------------
// Kernel 2: scores + pairs, 4-way h-split for occupancy.
// grid 512 = n(32) x a-tile(8, 16 a) x b-tile(2, 64 b); block 256:
//   tx = t&15 (patch col), ty = (t>>4)&3 (patch row), th = t>>6 (h group of 64).
// smem: xs 16KB resident + ys 16KB double-buffered; 4-way reduce in dead xs.
// ---------------------------------------------------------------------------
__global__ __launch_bounds__(256)
void pairwise_kernel(const float* __restrict__ W2,
                     const float* __restrict__ b2,
                     float* __restrict__ out,
                     int write_pairs)
{
    const int bid = blockIdx.x;
    const int n   = bid >> 4;
    const int at  = (bid >> 1) & 7;
    const int bt  = bid & 1;
    const int a0  = at * 16;
    const int b0  = bt * 64;
    const int t   = threadIdx.x;
    const int tx  = t & 15;
    const int ty  = (t >> 4) & 3;
    const int th  = t >> 6;

    __shared__ float4 xs4[256][4];       // [h][a-quad]  16KB
    __shared__ float4 ys4[2][32][16];    // [buf][h][b-quad]  16KB

#pragma unroll
    for (int r = 0; r < 4; r++) {
        int id = t + 256 * r;
        int hh = id >> 2, q = id & 3;
        xs4[hh][q] = *(const float4*)&g_hT[0][n][hh][a0 + q * 4];
    }
#pragma unroll
    for (int r = 0; r < 2; r++) {
        int id = t + 256 * r;
        int hh = id >> 4, q = id & 15;
        ys4[0][hh][q] = *(const float4*)&g_hT[1][n][hh][b0 + q * 4];
    }
    __syncthreads();

    float acc[4][4];
#pragma unroll
    for (int j = 0; j < 4; j++)
#pragma unroll
        for (int i = 0; i < 4; i++) acc[j][i] = 0.f;

    int buf = 0;
#pragma unroll 1
    for (int hc = 0; hc < 8; hc++) {
        float4 st[2];
        if (hc < 7) {
#pragma unroll
            for (int r = 0; r < 2; r++) {
                int id = t + 256 * r;
                int hh = id >> 4, q = id & 15;
                st[r] = *(const float4*)&g_hT[1][n][(hc + 1) * 32 + hh][b0 + q * 4];
            }
        }
#pragma unroll
        for (int u = 0; u < 8; u++) {
            int hh = th + u * 4;
            int hs = hc * 32 + hh;
            float  wv = __ldg(&W2[hs]);
            float4 x4 = xs4[hs][ty];
            float4 y4 = ys4[buf][hh][tx];
            float xa[4] = {x4.x, x4.y, x4.z, x4.w};
            float yb[4] = {y4.x, y4.y, y4.z, y4.w};
#pragma unroll
            for (int j = 0; j < 4; j++)
#pragma unroll
                for (int i = 0; i < 4; i++)
                    acc[j][i] = fmaf(fmaxf(xa[j] + yb[i], 0.f), wv, acc[j][i]);
        }
        if (hc < 7) {
            int nb = buf ^ 1;
#pragma unroll
            for (int r = 0; r < 2; r++) {
                int id = t + 256 * r;
                int hh = id >> 4, q = id & 15;
                ys4[nb][hh][q] = st[r];
            }
            __syncthreads();
            buf = nb;
        }
    }

    // 4-way reduction in dead xs region (16KB)
    float* red = (float*)&xs4[0][0];
    const int p = ty * 16 + tx;   // 0..63
    __syncthreads();
    if (th > 0) {
        int base = ((th - 1) * 64 + p) * 16;
#pragma unroll
        for (int j = 0; j < 4; j++)
#pragma unroll
            for (int i = 0; i < 4; i++) {
                int idx = j * 4 + i;
                red[base + ((idx + p) & 15)] = acc[j][i];
            }
    }
    __syncthreads();
    if (th == 0) {
        float s = 0.f;
#pragma unroll
        for (int j = 0; j < 4; j++)
#pragma unroll
            for (int i = 0; i < 4; i++) s += acc[j][i];
#pragma unroll
        for (int g = 0; g < 3; g++) {
            int base = (g * 64 + p) * 16;
#pragma unroll
            for (int idx = 0; idx < 16; idx++)
                s += red[base + ((idx + p) & 15)];
        }
        s += 16.f * __ldg(b2);
        const int m = at * 4 + ty;
        const int lcol = bt * 16 + tx;
        out[n * 1024 + m * 32 + lcol] = s;
    }

    if (write_pairs && t < 128) {
        int id    = bid * 128 + t;   // 0..65535
        int pi    = id >> 1;
        int which = id & 1;
        int idx   = pi & 1023;
        int v = which ? (idx & 31) : (idx >> 5);
        out[NUMG * 1024 + id] = (float)v;
    }
}

extern "C" void kernel_launch(void* const* d_in, const int* in_sizes, int n_in,
                              void* d_out, int out_size)
{
    const float* orig = (const float*)d_in[0];
    const int*   ind0 = (const int*)d_in[1];
    const int*   ind1 = (const int*)d_in[2];
    int i = 3;
    if (n_in >= 9 && in_sizes[3] == 1) i = 4;   // scalar k materialized
    const float* W1a = (const float*)d_in[i + 0];
    const float* W1b = (const float*)d_in[i + 1];
    const float* b1  = (const float*)d_in[i + 2];
    const float* W2  = (const float*)d_in[i + 3];
    const float* b2  = (const float*)d_in[i + 4];
    float* out = (float*)d_out;

    const int scores_elems = NUMG * 1024;
    const int pairs_elems  = NUMG * 1024 * 2;
    int write_pairs = (out_size >= scores_elems + pairs_elems) ? 1 : 0;

    const int DSM = 49152;   // Ahi/Alo 16KB + Bhi/Blo 8KB each
    cudaFuncSetAttribute(gemm_mma_kernel,
                         cudaFuncAttributeMaxDynamicSharedMemorySize, DSM);

    prep_w_kernel<<<32, 256>>>(W1a, W1b);
    gemm_mma_kernel<<<256, 256, DSM>>>(orig, ind0, ind1, b1);
    pairwise_kernel<<<512, 256>>>(W2, b2, out, write_pairs);
}

// round 8
// speedup vs baseline: 2.4759x; 1.0839x over previous
#include <cuda_runtime.h>
#include <cuda_bf16.h>
#include <cstdint>

// orig_fea [256, 300, 256] f32; ind0/ind1 [32,32,4] i32; W1a/W1b [256,256];
// b1[256]; W2[256,1]; b2[1]. L=128, pool=1200.
#define LN   128
#define DD   256
#define HH   256
#define NUMG 32
#define BAG  300

// Scratch: h0/h1 transposed: [side][n][h][a]  (8 MB)
__device__ float g_hT[2][NUMG][HH][LN];

// ============================ helpers ============================
__device__ __forceinline__ uint32_t smem_u32(const void* p) {
    uint32_t a;
    asm("{ .reg .u64 t; cvta.to.shared.u64 t, %1; cvt.u32.u64 %0, t; }"
        : "=r"(a) : "l"(p));
    return a;
}
// f32 pair -> bf16x2 (low half = x0); also return rounded values as f32
__device__ __forceinline__ uint32_t cvt_pair(float x0, float x1, float& h0f, float& h1f) {
    uint32_t r;
    asm("cvt.rn.bf16x2.f32 %0, %1, %2;" : "=r"(r) : "f"(x1), "f"(x0));
    h0f = __uint_as_float(r << 16);
    h1f = __uint_as_float(r & 0xFFFF0000u);
    return r;
}
__device__ __forceinline__ uint32_t cvt_pair_n(float x0, float x1) {
    uint32_t r;
    asm("cvt.rn.bf16x2.f32 %0, %1, %2;" : "=r"(r) : "f"(x1), "f"(x0));
    return r;
}
__device__ __forceinline__ void ldsm4(uint32_t* r, uint32_t addr) {
    asm volatile("ldmatrix.sync.aligned.m8n8.x4.shared.b16 {%0,%1,%2,%3}, [%4];"
        : "=r"(r[0]), "=r"(r[1]), "=r"(r[2]), "=r"(r[3]) : "r"(addr));
}
__device__ __forceinline__ void ldsm4t(uint32_t* r, uint32_t addr) {
    asm volatile("ldmatrix.sync.aligned.m8n8.x4.trans.shared.b16 {%0,%1,%2,%3}, [%4];"
        : "=r"(r[0]), "=r"(r[1]), "=r"(r[2]), "=r"(r[3]) : "r"(addr));
}
__device__ __forceinline__ void mma16816(float* d, const uint32_t* a,
                                         uint32_t b0, uint32_t b1) {
    asm volatile("mma.sync.aligned.m16n8k16.row.col.f32.bf16.bf16.f32 "
        "{%0,%1,%2,%3}, {%4,%5,%6,%7}, {%8,%9}, {%0,%1,%2,%3};"
        : "+f"(d[0]), "+f"(d[1]), "+f"(d[2]), "+f"(d[3])
        : "r"(a[0]), "r"(a[1]), "r"(a[2]), "r"(a[3]), "r"(b0), "r"(b1));
}
// XOR swizzle: rows of 128B, 16B atoms permuted by row%8 -> conflict-free LDSM
#define SWZ(row, kb) ((row) * 128 + ((kb) ^ (((row) & 7) << 4)))

// ---------------------------------------------------------------------------
// Kernel 1: mma.sync bf16 split-precision GEMM. W converted in-kernel:
// B staged from global [k][h] f32 -> smem [k][h] bf16 hi/lo (elementwise),
// B fragments via ldmatrix.trans (transpose in the load path, no prep kernel).
// grid 256 = side(2) x n(32) x h-quad(4, 64 h each). block 256 = 8 warps
// (warp_m 0..3 -> 32 a, warp_n 0..1 -> 32 h). K chunks of 64 in smem:
// Ahi/Alo [128 a][64 k] bf16 (16KB ea), Bhi/Blo [64 k][64 h] bf16 (8KB ea).
// ---------------------------------------------------------------------------
__global__ __launch_bounds__(256)
void gemm_mma_kernel(const float* __restrict__ orig,
                     const int*   __restrict__ ind0,
                     const int*   __restrict__ ind1,
                     const float* __restrict__ W1a,
                     const float* __restrict__ W1b,
                     const float* __restrict__ bias1)
{
    extern __shared__ char dsm[];
    __shared__ int rowoff[128];

    const int t = threadIdx.x, l = t & 31, w = t >> 5;
    const int b    = blockIdx.x;
    const int side = b >> 7;
    const int n    = (b >> 2) & 31;
    const int h0   = (b & 3) * 64;
    const int m0   = (w & 3) * 32;
    const int n0   = (w >> 2) * 32;
    const float* __restrict__ Wmat = side ? W1b : W1a;

    const uint32_t smb = smem_u32(dsm);
    const int offAhi = 0, offAlo = 16384, offBhi = 32768, offBlo = 40960;

    if (t < 128) {
        const int* __restrict__ ind = side ? ind1 : ind0;
        int p = ind[n * LN + t] + BAG * (t & 3);
        rowoff[t] = ((n * 2 + side) * 1200 + p) * DD;
    }
    __syncthreads();

    const int arow  = t >> 1;
    const int halfk = t & 1;
    const int ro    = rowoff[arow];
    const int bkr   = t >> 2;      // B stage: k row 0..63
    const int bhq   = t & 3;       // B stage: 16-h group

    float acc[2][4][4];
#pragma unroll
    for (int mt = 0; mt < 2; mt++)
#pragma unroll
        for (int nt = 0; nt < 4; nt++)
#pragma unroll
            for (int i = 0; i < 4; i++) acc[mt][nt][i] = 0.f;

#pragma unroll 1
    for (int c = 0; c < 4; c++) {
        // ---- stage A: 32 f32 per thread -> bf16 hi/lo, swizzled [a][k] ----
        {
            const float4* ap = (const float4*)(orig + ro + c * 64 + halfk * 32);
            float4 av[8];
#pragma unroll
            for (int q = 0; q < 8; q++) av[q] = ap[q];
#pragma unroll
            for (int q2 = 0; q2 < 4; q2++) {
                float4 u = av[2 * q2], v = av[2 * q2 + 1];
                float r0, r1, r2, r3, r4, r5, r6, r7;
                uint32_t hp0 = cvt_pair(u.x, u.y, r0, r1);
                uint32_t hp1 = cvt_pair(u.z, u.w, r2, r3);
                uint32_t hp2 = cvt_pair(v.x, v.y, r4, r5);
                uint32_t hp3 = cvt_pair(v.z, v.w, r6, r7);
                uint32_t lp0 = cvt_pair_n(u.x - r0, u.y - r1);
                uint32_t lp1 = cvt_pair_n(u.z - r2, u.w - r3);
                uint32_t lp2 = cvt_pair_n(v.x - r4, v.y - r5);
                uint32_t lp3 = cvt_pair_n(v.z - r6, v.w - r7);
                int kb = halfk * 64 + q2 * 16;
                *(uint4*)(dsm + offAhi + SWZ(arow, kb)) = make_uint4(hp0, hp1, hp2, hp3);
                *(uint4*)(dsm + offAlo + SWZ(arow, kb)) = make_uint4(lp0, lp1, lp2, lp3);
            }
        }
        // ---- stage B: W f32 [k][h] -> bf16 hi/lo smem [k][h] (no transpose) ----
        {
            const float4* wp = (const float4*)&Wmat[(c * 64 + bkr) * HH + h0 + bhq * 16];
            float4 wv[4];
#pragma unroll
            for (int q = 0; q < 4; q++) wv[q] = wp[q];
            uint32_t hi[8], lo[8];
#pragma unroll
            for (int q2 = 0; q2 < 2; q2++) {
                float4 u = wv[2 * q2], v = wv[2 * q2 + 1];
                float r0, r1, r2, r3, r4, r5, r6, r7;
                hi[q2 * 4 + 0] = cvt_pair(u.x, u.y, r0, r1);
                hi[q2 * 4 + 1] = cvt_pair(u.z, u.w, r2, r3);
                hi[q2 * 4 + 2] = cvt_pair(v.x, v.y, r4, r5);
                hi[q2 * 4 + 3] = cvt_pair(v.z, v.w, r6, r7);
                lo[q2 * 4 + 0] = cvt_pair_n(u.x - r0, u.y - r1);
                lo[q2 * 4 + 1] = cvt_pair_n(u.z - r2, u.w - r3);
                lo[q2 * 4 + 2] = cvt_pair_n(v.x - r4, v.y - r5);
                lo[q2 * 4 + 3] = cvt_pair_n(v.z - r6, v.w - r7);
            }
            int kb = bhq * 32;
            *(uint4*)(dsm + offBhi + SWZ(bkr, kb))      = make_uint4(hi[0], hi[1], hi[2], hi[3]);
            *(uint4*)(dsm + offBhi + SWZ(bkr, kb + 16)) = make_uint4(hi[4], hi[5], hi[6], hi[7]);
            *(uint4*)(dsm + offBlo + SWZ(bkr, kb))      = make_uint4(lo[0], lo[1], lo[2], lo[3]);
            *(uint4*)(dsm + offBlo + SWZ(bkr, kb + 16)) = make_uint4(lo[4], lo[5], lo[6], lo[7]);
        }
        __syncthreads();

        // ---- compute: 4 k16 steps ----
#pragma unroll
        for (int ks = 0; ks < 4; ks++) {
            const int rA  = m0 + (l & 15);
            const int kbL = ks * 32 + ((l >> 4) << 4);
            uint32_t ahi[2][4], alo[2][4], bhi[2][4], blo[2][4];
            ldsm4(ahi[0], smb + offAhi + SWZ(rA, kbL));
            ldsm4(ahi[1], smb + offAhi + SWZ(rA + 16, kbL));
            ldsm4(alo[0], smb + offAlo + SWZ(rA, kbL));
            ldsm4(alo[1], smb + offAlo + SWZ(rA + 16, kbL));
            // B trans-ldsm: rows = k, cols = h; tiles land as
            // {b0(n..n+7), b1(n..n+7), b0(n+8..n+15), b1(n+8..n+15)}
            const int rK = ks * 16 + (l & 15);
            const int hb = ((l >> 4) << 4);
            ldsm4t(bhi[0], smb + offBhi + SWZ(rK, n0 * 2 + hb));
            ldsm4t(bhi[1], smb + offBhi + SWZ(rK, n0 * 2 + 32 + hb));
            ldsm4t(blo[0], smb + offBlo + SWZ(rK, n0 * 2 + hb));
            ldsm4t(blo[1], smb + offBlo + SWZ(rK, n0 * 2 + 32 + hb));
#pragma unroll
            for (int mt = 0; mt < 2; mt++)
#pragma unroll
                for (int g = 0; g < 2; g++)
#pragma unroll
                    for (int s = 0; s < 2; s++) {
                        int nt = g * 2 + s;
                        mma16816(acc[mt][nt], ahi[mt], bhi[g][2 * s], bhi[g][2 * s + 1]);
                        mma16816(acc[mt][nt], alo[mt], bhi[g][2 * s], bhi[g][2 * s + 1]);
                        mma16816(acc[mt][nt], ahi[mt], blo[g][2 * s], blo[g][2 * s + 1]);
                    }
        }
        __syncthreads();
    }

    // ---- epilogue: write transposed to g_hT (+b1 on side 0) ----
    const int g    = l >> 2;
    const int tid4 = l & 3;
#pragma unroll
    for (int mt = 0; mt < 2; mt++) {
        int ag = m0 + mt * 16 + g;
#pragma unroll
        for (int nt = 0; nt < 4; nt++) {
            int hg = h0 + n0 + nt * 8 + tid4 * 2;
            float bv0 = 0.f, bv1 = 0.f;
            if (side == 0) { bv0 = __ldg(&bias1[hg]); bv1 = __ldg(&bias1[hg + 1]); }
            g_hT[side][n][hg    ][ag    ] = acc[mt][nt][0] + bv0;
            g_hT[side][n][hg + 1][ag    ] = acc[mt][nt][1] + bv1;
            g_hT[side][n][hg    ][ag + 8] = acc[mt][nt][2] + bv0;
            g_hT[side][n][hg + 1][ag + 8] = acc[mt][nt][3] + bv1;
        }
    }
}

// ---------------------------------------------------------------------------
// Kernel 2: scores + pairs, 4-way h-split for occupancy (unchanged from R7).
// grid 512 = n(32) x a-tile(8, 16 a) x b-tile(2, 64 b); block 256.
// ---------------------------------------------------------------------------
__global__ __launch_bounds__(256)
void pairwise_kernel(const float* __restrict__ W2,
                     const float* __restrict__ b2,
                     float* __restrict__ out,
                     int write_pairs)
{
    const int bid = blockIdx.x;
    const int n   = bid >> 4;
    const int at  = (bid >> 1) & 7;
    const int bt  = bid & 1;
    const int a0  = at * 16;
    const int b0  = bt * 64;
    const int t   = threadIdx.x;
    const int tx  = t & 15;
    const int ty  = (t >> 4) & 3;
    const int th  = t >> 6;

    __shared__ float4 xs4[256][4];       // [h][a-quad]  16KB
    __shared__ float4 ys4[2][32][16];    // [buf][h][b-quad]  16KB

#pragma unroll
    for (int r = 0; r < 4; r++) {
        int id = t + 256 * r;
        int hh = id >> 2, q = id & 3;
        xs4[hh][q] = *(const float4*)&g_hT[0][n][hh][a0 + q * 4];
    }
#pragma unroll
    for (int r = 0; r < 2; r++) {
        int id = t + 256 * r;
        int hh = id >> 4, q = id & 15;
        ys4[0][hh][q] = *(const float4*)&g_hT[1][n][hh][b0 + q * 4];
    }
    __syncthreads();

    float acc[4][4];
#pragma unroll
    for (int j = 0; j < 4; j++)
#pragma unroll
        for (int i = 0; i < 4; i++) acc[j][i] = 0.f;

    int buf = 0;
#pragma unroll 1
    for (int hc = 0; hc < 8; hc++) {
        float4 st[2];
        if (hc < 7) {
#pragma unroll
            for (int r = 0; r < 2; r++) {
                int id = t + 256 * r;
                int hh = id >> 4, q = id & 15;
                st[r] = *(const float4*)&g_hT[1][n][(hc + 1) * 32 + hh][b0 + q * 4];
            }
        }
#pragma unroll
        for (int u = 0; u < 8; u++) {
            int hh = th + u * 4;
            int hs = hc * 32 + hh;
            float  wv = __ldg(&W2[hs]);
            float4 x4 = xs4[hs][ty];
            float4 y4 = ys4[buf][hh][tx];
            float xa[4] = {x4.x, x4.y, x4.z, x4.w};
            float yb[4] = {y4.x, y4.y, y4.z, y4.w};
#pragma unroll
            for (int j = 0; j < 4; j++)
#pragma unroll
                for (int i = 0; i < 4; i++)
                    acc[j][i] = fmaf(fmaxf(xa[j] + yb[i], 0.f), wv, acc[j][i]);
        }
        if (hc < 7) {
            int nb = buf ^ 1;
#pragma unroll
            for (int r = 0; r < 2; r++) {
                int id = t + 256 * r;
                int hh = id >> 4, q = id & 15;
                ys4[nb][hh][q] = st[r];
            }
            __syncthreads();
            buf = nb;
        }
    }

    // 4-way reduction in dead xs region (16KB)
    float* red = (float*)&xs4[0][0];
    const int p = ty * 16 + tx;   // 0..63
    __syncthreads();
    if (th > 0) {
        int base = ((th - 1) * 64 + p) * 16;
#pragma unroll
        for (int j = 0; j < 4; j++)
#pragma unroll
            for (int i = 0; i < 4; i++) {
                int idx = j * 4 + i;
                red[base + ((idx + p) & 15)] = acc[j][i];
            }
    }
    __syncthreads();
    if (th == 0) {
        float s = 0.f;
#pragma unroll
        for (int j = 0; j < 4; j++)
#pragma unroll
            for (int i = 0; i < 4; i++) s += acc[j][i];
#pragma unroll
        for (int g = 0; g < 3; g++) {
            int base = (g * 64 + p) * 16;
#pragma unroll
            for (int idx = 0; idx < 16; idx++)
                s += red[base + ((idx + p) & 15)];
        }
        s += 16.f * __ldg(b2);
        const int m = at * 4 + ty;
        const int lcol = bt * 16 + tx;
        out[n * 1024 + m * 32 + lcol] = s;
    }

    if (write_pairs && t < 128) {
        int id    = bid * 128 + t;   // 0..65535
        int pi    = id >> 1;
        int which = id & 1;
        int idx   = pi & 1023;
        int v = which ? (idx & 31) : (idx >> 5);
        out[NUMG * 1024 + id] = (float)v;
    }
}

extern "C" void kernel_launch(void* const* d_in, const int* in_sizes, int n_in,
                              void* d_out, int out_size)
{
    const float* orig = (const float*)d_in[0];
    const int*   ind0 = (const int*)d_in[1];
    const int*   ind1 = (const int*)d_in[2];
    int i = 3;
    if (n_in >= 9 && in_sizes[3] == 1) i = 4;   // scalar k materialized
    const float* W1a = (const float*)d_in[i + 0];
    const float* W1b = (const float*)d_in[i + 1];
    const float* b1  = (const float*)d_in[i + 2];
    const float* W2  = (const float*)d_in[i + 3];
    const float* b2  = (const float*)d_in[i + 4];
    float* out = (float*)d_out;

    const int scores_elems = NUMG * 1024;
    const int pairs_elems  = NUMG * 1024 * 2;
    int write_pairs = (out_size >= scores_elems + pairs_elems) ? 1 : 0;

    const int DSM = 49152;   // Ahi/Alo 16KB + Bhi/Blo 8KB each
    cudaFuncSetAttribute(gemm_mma_kernel,
                         cudaFuncAttributeMaxDynamicSharedMemorySize, DSM);

    gemm_mma_kernel<<<256, 256, DSM>>>(orig, ind0, ind1, W1a, W1b, b1);
    pairwise_kernel<<<512, 256>>>(W2, b2, out, write_pairs);
}